// round 11
// baseline (speedup 1.0000x reference)
#include <cuda_runtime.h>
#include <cstdint>

#define BATCH 2048
#define D0 256
#define D1 256
#define D2 256
#define D3 128
#define NSLAB 8              // 256 k-values / 32 per layer-1 CTA column-block

// Scratch (device globals: allocation-free per harness rules)
__device__ float g_We0[D1 * D0];
__device__ float g_We1[D2 * D1];
__device__ float g_We2T[D2 * D3];              // [k][o] transposed last-layer weights
__device__ float g_h1[BATCH * D1];
__device__ float g_part[NSLAB * BATCH * D3];   // 8.4 MB partial sums

__device__ __forceinline__ float tanh_fast(float x) {
    float y;
    asm("tanh.approx.f32 %0, %1;" : "=f"(y) : "f"(x));
    return y;
}

__device__ __forceinline__ float atom_apply(float w, int idx) {
    float v = w;                       // identity
    if (idx == 1)      v = sinf(w);
    else if (idx == 2) v = tanhf(w);
    else if (idx == 3) v = w * w;
    return v;
}

// Precompute effective weights. We2 is stored TRANSPOSED ([k][o]) for the
// fused epilogue in layer 1.
__global__ void prep_we_kernel(const float* __restrict__ W0, const int* __restrict__ f0,
                               const float* __restrict__ W1, const int* __restrict__ f1,
                               const float* __restrict__ W2, const int* __restrict__ f2) {
    const int n01 = D1 * D0;           // 65536
    const int n2  = D3 * D2;           // 32768
    const int stride = gridDim.x * blockDim.x;
    for (int t = blockIdx.x * blockDim.x + threadIdx.x; t < n01; t += stride) {
        g_We0[t] = atom_apply(W0[t], f0[t]);
        g_We1[t] = atom_apply(W1[t], f1[t]);
    }
    for (int t = blockIdx.x * blockDim.x + threadIdx.x; t < n2; t += stride) {
        int o = t >> 8;                // W2 is [128][256] row-major
        int k = t & 255;
        g_We2T[k * D3 + o] = atom_apply(W2[t], f2[t]);
    }
}

// Layer 0: h1[b,o] = sum_i tanh(x[b,i]*We0[o,i]) + b0[o]. MUFU-bound, at floor.
template <int IN>
__global__ __launch_bounds__(256) void layer_tanh_kernel(
    const float* __restrict__ h_in,   // [BATCH, IN]
    const float* __restrict__ We,     // [OUT, IN]
    const float* __restrict__ bias,   // [OUT]
    float* __restrict__ h_out,        // [BATCH, OUT]
    int OUT) {
    __shared__ float We_s[IN][33];
    __shared__ float h_s[8][IN];

    const int tx = threadIdx.x;
    const int ty = threadIdx.y;
    const int tid = ty * 32 + tx;
    const int o0 = blockIdx.x * 32;
    const int b0 = blockIdx.y * 8;

    for (int idx = tid; idx < 32 * IN; idx += 256) {
        int o = idx / IN;
        int i = idx - o * IN;
        We_s[i][o] = We[(o0 + o) * IN + i];
    }
    const float4* Hg = reinterpret_cast<const float4*>(h_in + b0 * IN);
    float4* Hs = reinterpret_cast<float4*>(&h_s[0][0]);
    for (int idx = tid; idx < 8 * IN / 4; idx += 256) {
        Hs[idx] = Hg[idx];
    }
    __syncthreads();

    float acc0 = 0.f, acc1 = 0.f;
#pragma unroll 8
    for (int i = 0; i < IN; i += 2) {
        float z0 = h_s[ty][i]     * We_s[i][tx];
        float z1 = h_s[ty][i + 1] * We_s[i + 1][tx];
        acc0 += tanh_fast(z0);
        acc1 += tanh_fast(z1);
    }
    h_out[(b0 + ty) * OUT + o0 + tx] = acc0 + acc1 + bias[o0 + tx];
}

// Layer 1 FUSED with last-layer partials:
//   h2_tile[8b x 32k] computed in registers (MUFU tanh), then immediately
//   multiplied by We2T[32k x 128o] (staged in smem) on the idle FMA pipe.
//   Writes part[slab][b][128] where slab = blockIdx.x; h2 never hits gmem.
__global__ __launch_bounds__(256) void layer1_fused_kernel(
    const float* __restrict__ h_in,   // [BATCH, 256] = h1
    const float* __restrict__ We,     // [256, 256] = We1
    const float* __restrict__ bias,   // [256] = b1
    const float* __restrict__ We2T,   // [256, 128] k-major
    float* __restrict__ part) {       // [8][BATCH][128]
    constexpr int IN = D1;
    __shared__ float We_s[IN][33];    // 33.8 KB
    __shared__ float h_s[8][IN];      //  8.2 KB
    __shared__ float W2T_s[32][132];  // 16.9 KB (pad 132: bank (4k+c)%32, lanes distinct)
    __shared__ float h2_s[8][33];     //  1.1 KB

    const int tx = threadIdx.x;
    const int ty = threadIdx.y;
    const int tid = ty * 32 + tx;
    const int o0 = blockIdx.x * 32;   // this CTA's 32 h2 columns = lin k-range
    const int b0 = blockIdx.y * 8;

    for (int idx = tid; idx < 32 * IN; idx += 256) {
        int o = idx / IN;
        int i = idx - o * IN;
        We_s[i][o] = We[(o0 + o) * IN + i];
    }
    const float4* Hg = reinterpret_cast<const float4*>(h_in + b0 * IN);
    float4* Hs = reinterpret_cast<float4*>(&h_s[0][0]);
    for (int idx = tid; idx < 8 * IN / 4; idx += 256) {
        Hs[idx] = Hg[idx];
    }
    // Stage We2T rows o0..o0+31 ([32][128], gmem coalesced over o).
    for (int idx = tid; idx < 32 * D3; idx += 256) {
        int k = idx >> 7;             // /128
        int o = idx & 127;
        W2T_s[k][o] = We2T[(o0 + k) * D3 + o];
    }
    __syncthreads();

    float acc0 = 0.f, acc1 = 0.f;
#pragma unroll 8
    for (int i = 0; i < IN; i += 2) {
        float z0 = h_s[ty][i]     * We_s[i][tx];
        float z1 = h_s[ty][i + 1] * We_s[i + 1][tx];
        acc0 += tanh_fast(z0);
        acc1 += tanh_fast(z1);
    }
    h2_s[ty][tx] = acc0 + acc1 + bias[o0 + tx];
    __syncthreads();

    // Partial last layer: p[b, o] = sum_{k<32} h2_s[b][k] * W2T_s[k][o]
    float p0 = 0.f, p1 = 0.f, p2 = 0.f, p3 = 0.f;
#pragma unroll
    for (int k = 0; k < 32; k++) {
        float hv = h2_s[ty][k];                 // warp-uniform broadcast
        p0 += hv * W2T_s[k][tx];                // lanes -> distinct banks
        p1 += hv * W2T_s[k][32 + tx];
        p2 += hv * W2T_s[k][64 + tx];
        p3 += hv * W2T_s[k][96 + tx];
    }
    float* pb = part + ((size_t)blockIdx.x * BATCH + (b0 + ty)) * D3;
    pb[tx]      = p0;
    pb[32 + tx] = p1;
    pb[64 + tx] = p2;
    pb[96 + tx] = p3;
}

// Final reduce: out[b,o] = sum_slabs part[s][b][o] + b2[o]. ~9MB traffic.
__global__ __launch_bounds__(256) void reduce_kernel(
    const float* __restrict__ part,   // [8][BATCH][128]
    const float* __restrict__ b2,     // [128]
    float* __restrict__ out) {        // [BATCH, 128]
    int idx = blockIdx.x * 256 + threadIdx.x;   // 0 .. 2048*128-1
    int o = idx & 127;
    float s = b2[o];
#pragma unroll
    for (int j = 0; j < NSLAB; j++)
        s += part[(size_t)j * BATCH * D3 + idx];
    out[idx] = s;
}

extern "C" void kernel_launch(void* const* d_in, const int* in_sizes, int n_in,
                              void* d_out, int out_size) {
    // Resolve input ordering at runtime (dict vs signature order).
    const float *x, *W0, *b0, *W1, *b1, *W2, *b2;
    const int *f0, *f1, *f2;
    x = (const float*)d_in[0];
    if (in_sizes[4] == 256) {
        // signature order: x, W0,b0, W1,b1, W2,b2, f0,f1,f2
        W0 = (const float*)d_in[1]; b0 = (const float*)d_in[2];
        W1 = (const float*)d_in[3]; b1 = (const float*)d_in[4];
        W2 = (const float*)d_in[5]; b2 = (const float*)d_in[6];
        f0 = (const int*)d_in[7];  f1 = (const int*)d_in[8];  f2 = (const int*)d_in[9];
    } else {
        // dict order: x, W0,b0,f0, W1,b1,f1, W2,b2,f2
        W0 = (const float*)d_in[1]; b0 = (const float*)d_in[2]; f0 = (const int*)d_in[3];
        W1 = (const float*)d_in[4]; b1 = (const float*)d_in[5]; f1 = (const int*)d_in[6];
        W2 = (const float*)d_in[7]; b2 = (const float*)d_in[8]; f2 = (const int*)d_in[9];
    }

    float *dWe0, *dWe1, *dWe2T, *dh1, *dpart;
    cudaGetSymbolAddress((void**)&dWe0, g_We0);
    cudaGetSymbolAddress((void**)&dWe1, g_We1);
    cudaGetSymbolAddress((void**)&dWe2T, g_We2T);
    cudaGetSymbolAddress((void**)&dh1, g_h1);
    cudaGetSymbolAddress((void**)&dpart, g_part);

    float* out = (float*)d_out;

    prep_we_kernel<<<256, 256>>>(W0, f0, W1, f1, W2, f2);

    dim3 blk(32, 8);
    // Layer 0: x -> h1 (MUFU tanh, at floor)
    layer_tanh_kernel<D0><<<dim3(D1 / 32, BATCH / 8), blk>>>(x, dWe0, b0, dh1, D1);
    // Layer 1 + fused last-layer partials: h1 -> part slabs
    layer1_fused_kernel<<<dim3(D2 / 32, BATCH / 8), blk>>>(dh1, dWe1, b1, dWe2T, dpart);
    // Reduce slabs + bias -> out
    reduce_kernel<<<(BATCH * D3) / 256, 256>>>(dpart, b2, out);
}

// round 12
// speedup vs baseline: 1.1098x; 1.1098x over previous
#include <cuda_runtime.h>
#include <cstdint>

#define BATCH 2048
#define D0 256
#define D1 256
#define D2 256
#define D3 128
#define NSLAB 8              // 256 h2-columns / 32 per layer-1 CTA

// Scratch (device globals: allocation-free per harness rules)
__device__ float g_We0[D1 * D0];
__device__ float g_We1[D2 * D1];
__device__ float g_We2T[D2 * D3];              // [k][o] transposed last-layer weights
__device__ float g_h1[BATCH * D1];
__device__ float g_part[NSLAB * BATCH * D3];   // 8.4 MB partial sums

__device__ __forceinline__ float tanh_fast(float x) {
    float y;
    asm("tanh.approx.f32 %0, %1;" : "=f"(y) : "f"(x));
    return y;
}

__device__ __forceinline__ float atom_apply(float w, int idx) {
    float v = w;                       // identity
    if (idx == 1)      v = sinf(w);
    else if (idx == 2) v = tanhf(w);
    else if (idx == 3) v = w * w;
    return v;
}

// Precompute effective weights. We2 stored TRANSPOSED ([k][o]) for the epilogue.
__global__ void prep_we_kernel(const float* __restrict__ W0, const int* __restrict__ f0,
                               const float* __restrict__ W1, const int* __restrict__ f1,
                               const float* __restrict__ W2, const int* __restrict__ f2) {
    const int n01 = D1 * D0;           // 65536
    const int n2  = D3 * D2;           // 32768
    const int stride = gridDim.x * blockDim.x;
    for (int t = blockIdx.x * blockDim.x + threadIdx.x; t < n01; t += stride) {
        g_We0[t] = atom_apply(W0[t], f0[t]);
        g_We1[t] = atom_apply(W1[t], f1[t]);
    }
    for (int t = blockIdx.x * blockDim.x + threadIdx.x; t < n2; t += stride) {
        int o = t >> 8;                // W2 is [128][256] row-major
        int k = t & 255;
        g_We2T[k * D3 + o] = atom_apply(W2[t], f2[t]);
    }
}

// Layer 0: h1[b,o] = sum_i tanh(x[b,i]*We0[o,i]) + b0[o]. MUFU-bound, at floor.
template <int IN>
__global__ __launch_bounds__(256) void layer_tanh_kernel(
    const float* __restrict__ h_in,   // [BATCH, IN]
    const float* __restrict__ We,     // [OUT, IN]
    const float* __restrict__ bias,   // [OUT]
    float* __restrict__ h_out,        // [BATCH, OUT]
    int OUT) {
    __shared__ float We_s[IN][33];
    __shared__ float h_s[8][IN];

    const int tx = threadIdx.x;
    const int ty = threadIdx.y;
    const int tid = ty * 32 + tx;
    const int o0 = blockIdx.x * 32;
    const int b0 = blockIdx.y * 8;

    for (int idx = tid; idx < 32 * IN; idx += 256) {
        int o = idx / IN;
        int i = idx - o * IN;
        We_s[i][o] = We[(o0 + o) * IN + i];
    }
    const float4* Hg = reinterpret_cast<const float4*>(h_in + b0 * IN);
    float4* Hs = reinterpret_cast<float4*>(&h_s[0][0]);
    for (int idx = tid; idx < 8 * IN / 4; idx += 256) {
        Hs[idx] = Hg[idx];
    }
    __syncthreads();

    float acc0 = 0.f, acc1 = 0.f;
#pragma unroll 8
    for (int i = 0; i < IN; i += 2) {
        float z0 = h_s[ty][i]     * We_s[i][tx];
        float z1 = h_s[ty][i + 1] * We_s[i + 1][tx];
        acc0 += tanh_fast(z0);
        acc1 += tanh_fast(z1);
    }
    h_out[(b0 + ty) * OUT + o0 + tx] = acc0 + acc1 + bias[o0 + tx];
}

// Layer 1 fused v2: 32-batch tile. CTA (bx,by) computes h2[32b x 32k] in regs
// (4 batches/thread -> each We LDS reused 4x; MUFU-bound), then multiplies by
// We2T[32k x 128o] (1B LDS per FFMA at this tile size) into part[bx][b][o].
// Dynamic smem: We_s 33.8K + h_s 32K + W2T 16.4K + h2 4.1K = 85K -> 2 CTAs/SM.
__global__ __launch_bounds__(256) void layer1_fused_kernel(
    const float* __restrict__ h_in,   // [BATCH, 256] = h1
    const float* __restrict__ We,     // [256, 256] = We1
    const float* __restrict__ bias,   // [256] = b1
    const float* __restrict__ We2T,   // [256, 128] k-major
    float* __restrict__ part) {       // [8][BATCH][128]
    constexpr int IN = D1;
    extern __shared__ float sh[];
    float* We_s  = sh;                      // [256][33]  8448 floats
    float* h_s   = sh + 8448;               // [32][256]  8192 floats
    float* W2T_s = sh + 8448 + 8192;        // [32][128]  4096 floats
    float* h2_s  = sh + 8448 + 8192 + 4096; // [32][32]   1024 floats

    const int tx = threadIdx.x;
    const int ty = threadIdx.y;
    const int tid = ty * 32 + tx;
    const int o0 = blockIdx.x * 32;   // h2 column block = lin k-range
    const int b0 = blockIdx.y * 32;

    // Stage We1 tile transposed: We_s[i][o] (STS banks = i -> conflict-free).
    for (int idx = tid; idx < 32 * IN; idx += 256) {
        int o = idx / IN;
        int i = idx - o * IN;
        We_s[i * 33 + o] = We[(o0 + o) * IN + i];
    }
    // Stage h1 tile [32][256], float4.
    {
        const float4* Hg = reinterpret_cast<const float4*>(h_in + b0 * IN);
        float4* Hs = reinterpret_cast<float4*>(h_s);
        for (int idx = tid; idx < 32 * IN / 4; idx += 256)
            Hs[idx] = Hg[idx];
    }
    // Stage We2T rows o0..o0+31: W2T_s[k][o], gmem coalesced over o.
    for (int idx = tid; idx < 32 * D3; idx += 256) {
        int k = idx >> 7;
        int o = idx & 127;
        W2T_s[k * D3 + o] = We2T[(o0 + k) * D3 + o];
    }
    __syncthreads();

    // Mainloop: thread (tx, ty) -> h2 column tx, batches ty+8j (j=0..3).
    float acc[4] = {0.f, 0.f, 0.f, 0.f};
#pragma unroll 4
    for (int i = 0; i < IN; i += 2) {
        float w0 = We_s[i * 33 + tx];         // lanes -> consecutive banks
        float w1 = We_s[(i + 1) * 33 + tx];
#pragma unroll
        for (int j = 0; j < 4; j++) {
            float2 hp = *reinterpret_cast<const float2*>(&h_s[(ty + 8 * j) * IN + i]); // bcast
            acc[j] += tanh_fast(hp.x * w0);
            acc[j] += tanh_fast(hp.y * w1);
        }
    }
    float bb = bias[o0 + tx];
#pragma unroll
    for (int j = 0; j < 4; j++)
        h2_s[(ty + 8 * j) * 32 + tx] = acc[j] + bb;   // lanes consecutive, conflict-free
    __syncthreads();

    // Epilogue: partial lin. Thread -> outputs {tx+32m}, batches {ty+8j}.
    float p[4][4];
#pragma unroll
    for (int j = 0; j < 4; j++)
#pragma unroll
        for (int m = 0; m < 4; m++) p[j][m] = 0.f;

#pragma unroll 8
    for (int k = 0; k < 32; k++) {
        float w0 = W2T_s[k * D3 + tx];
        float w1 = W2T_s[k * D3 + 32 + tx];
        float w2 = W2T_s[k * D3 + 64 + tx];
        float w3 = W2T_s[k * D3 + 96 + tx];
#pragma unroll
        for (int j = 0; j < 4; j++) {
            float hv = h2_s[(ty + 8 * j) * 32 + k];   // bcast
            p[j][0] += hv * w0;
            p[j][1] += hv * w1;
            p[j][2] += hv * w2;
            p[j][3] += hv * w3;
        }
    }
    // Store partials: part[slab=bx][b0+b][o], coalesced over tx.
    float* ps = part + ((size_t)blockIdx.x * BATCH + b0) * D3;
#pragma unroll
    for (int j = 0; j < 4; j++) {
        float* pr = ps + (ty + 8 * j) * D3;
#pragma unroll
        for (int m = 0; m < 4; m++)
            pr[m * 32 + tx] = p[j][m];
    }
}

// Final reduce: out[b,o] = sum_slabs part[s][b][o] + b2[o]. float4, unrolled.
__global__ __launch_bounds__(256) void reduce_kernel(
    const float* __restrict__ part,   // [8][BATCH][128]
    const float* __restrict__ b2,     // [128]
    float* __restrict__ out) {        // [BATCH, 128]
    int idx = blockIdx.x * 256 + threadIdx.x;       // float4 index, 0..65535
    const float4* p4 = reinterpret_cast<const float4*>(part);
    float4 s = reinterpret_cast<const float4*>(b2)[idx & 31];
#pragma unroll
    for (int j = 0; j < NSLAB; j++) {
        float4 v = p4[(size_t)j * (BATCH * D3 / 4) + idx];
        s.x += v.x; s.y += v.y; s.z += v.z; s.w += v.w;
    }
    reinterpret_cast<float4*>(out)[idx] = s;
}

extern "C" void kernel_launch(void* const* d_in, const int* in_sizes, int n_in,
                              void* d_out, int out_size) {
    // Resolve input ordering at runtime (dict vs signature order).
    const float *x, *W0, *b0, *W1, *b1, *W2, *b2;
    const int *f0, *f1, *f2;
    x = (const float*)d_in[0];
    if (in_sizes[4] == 256) {
        // signature order: x, W0,b0, W1,b1, W2,b2, f0,f1,f2
        W0 = (const float*)d_in[1]; b0 = (const float*)d_in[2];
        W1 = (const float*)d_in[3]; b1 = (const float*)d_in[4];
        W2 = (const float*)d_in[5]; b2 = (const float*)d_in[6];
        f0 = (const int*)d_in[7];  f1 = (const int*)d_in[8];  f2 = (const int*)d_in[9];
    } else {
        // dict order: x, W0,b0,f0, W1,b1,f1, W2,b2,f2
        W0 = (const float*)d_in[1]; b0 = (const float*)d_in[2]; f0 = (const int*)d_in[3];
        W1 = (const float*)d_in[4]; b1 = (const float*)d_in[5]; f1 = (const int*)d_in[6];
        W2 = (const float*)d_in[7]; b2 = (const float*)d_in[8]; f2 = (const int*)d_in[9];
    }

    float *dWe0, *dWe1, *dWe2T, *dh1, *dpart;
    cudaGetSymbolAddress((void**)&dWe0, g_We0);
    cudaGetSymbolAddress((void**)&dWe1, g_We1);
    cudaGetSymbolAddress((void**)&dWe2T, g_We2T);
    cudaGetSymbolAddress((void**)&dh1, g_h1);
    cudaGetSymbolAddress((void**)&dpart, g_part);

    float* out = (float*)d_out;

    // 85 KB dynamic smem for the fused kernel (idempotent; no allocation).
    const int fused_smem = (8448 + 8192 + 4096 + 1024) * (int)sizeof(float); // 87040 B
    cudaFuncSetAttribute(layer1_fused_kernel,
                         cudaFuncAttributeMaxDynamicSharedMemorySize, fused_smem);

    prep_we_kernel<<<256, 256>>>(W0, f0, W1, f1, W2, f2);

    dim3 blk(32, 8);
    // Layer 0: x -> h1 (MUFU tanh, at floor)
    layer_tanh_kernel<D0><<<dim3(D1 / 32, BATCH / 8), blk>>>(x, dWe0, b0, dh1, D1);
    // Layer 1 + fused last layer: h1 -> part slabs (grid 8 x 64 = 512 CTAs)
    layer1_fused_kernel<<<dim3(D2 / 32, BATCH / 32), blk, fused_smem>>>(
        dh1, dWe1, b1, dWe2T, dpart);
    // Reduce slabs + bias -> out (float4, 256 CTAs)
    reduce_kernel<<<(BATCH * D3 / 4) / 256, 256>>>(dpart, b2, out);
}

// round 13
// speedup vs baseline: 1.1420x; 1.0291x over previous
#include <cuda_runtime.h>
#include <cstdint>

#define BATCH 2048
#define D0 256
#define D1 256
#define D2 256
#define D3 128

// Scratch (device globals: allocation-free per harness rules)
__device__ float g_We0[D1 * D0];
__device__ float g_We1[D2 * D1];
__device__ float g_We2[D3 * D2];
__device__ float g_h1[BATCH * D1];
__device__ float g_h2[BATCH * D2];

__device__ __forceinline__ float tanh_fast(float x) {
    float y;
    asm("tanh.approx.f32 %0, %1;" : "=f"(y) : "f"(x));
    return y;
}

__device__ __forceinline__ float atom_apply(float w, int idx) {
    float v = w;                       // identity
    if (idx == 1)      v = sinf(w);
    else if (idx == 2) v = tanhf(w);
    else if (idx == 3) v = w * w;
    return v;
}

// Precompute effective weights We = atom(W, idx) for all three layers.
__global__ void prep_we_kernel(const float* __restrict__ W0, const int* __restrict__ f0,
                               const float* __restrict__ W1, const int* __restrict__ f1,
                               const float* __restrict__ W2, const int* __restrict__ f2) {
    const int n01 = D1 * D0;           // 65536
    const int n2  = D3 * D2;           // 32768
    const int stride = gridDim.x * blockDim.x;
    for (int t = blockIdx.x * blockDim.x + threadIdx.x; t < n01; t += stride) {
        g_We0[t] = atom_apply(W0[t], f0[t]);
        g_We1[t] = atom_apply(W1[t], f1[t]);
    }
    for (int t = blockIdx.x * blockDim.x + threadIdx.x; t < n2; t += stride) {
        g_We2[t] = atom_apply(W2[t], f2[t]);
    }
}

// Hidden layer: h_out[b,o] = sum_i tanh(h[b,i]*We[o,i]) + bias[o]
// MUFU-bound (tanh.approx.f32, 16 elem/cyc/SM) — measured at floor; unchanged.
template <int IN>
__global__ __launch_bounds__(256) void layer_tanh_kernel(
    const float* __restrict__ h_in,   // [BATCH, IN]
    const float* __restrict__ We,     // [OUT, IN]
    const float* __restrict__ bias,   // [OUT]
    float* __restrict__ h_out,        // [BATCH, OUT]
    int OUT) {
    __shared__ float We_s[IN][33];
    __shared__ float h_s[8][IN];

    const int tx = threadIdx.x;
    const int ty = threadIdx.y;
    const int tid = ty * 32 + tx;
    const int o0 = blockIdx.x * 32;
    const int b0 = blockIdx.y * 8;

    for (int idx = tid; idx < 32 * IN; idx += 256) {
        int o = idx / IN;
        int i = idx - o * IN;
        We_s[i][o] = We[(o0 + o) * IN + i];
    }
    const float4* Hg = reinterpret_cast<const float4*>(h_in + b0 * IN);
    float4* Hs = reinterpret_cast<float4*>(&h_s[0][0]);
    for (int idx = tid; idx < 8 * IN / 4; idx += 256) {
        Hs[idx] = Hg[idx];
    }
    __syncthreads();

    float acc0 = 0.f, acc1 = 0.f;
#pragma unroll 8
    for (int i = 0; i < IN; i += 2) {
        float z0 = h_s[ty][i]     * We_s[i][tx];
        float z1 = h_s[ty][i + 1] * We_s[i + 1][tx];
        acc0 += tanh_fast(z0);
        acc1 += tanh_fast(z1);
    }
    h_out[(b0 + ty) * OUT + o0 + tx] = acc0 + acc1 + bias[o0 + tx];
}

// Last layer (identity): fp32 GEMM, 32o x 16b tiles, grid 512.
// Explicitly software-pipelined inner loop: prefetch k+4's three float4s into
// "next" registers before issuing k's 12 FMAs -> LDS latency (29cyc) hidden
// behind independent FMA work instead of stalling each iteration.
__global__ __launch_bounds__(256) void layer_lin_kernel(
    const float* __restrict__ h_in,     // [BATCH, 256]
    const float* __restrict__ We,       // [128, 256]
    const float* __restrict__ bias,     // [128]
    float* __restrict__ out) {          // [BATCH, 128]
    constexpr int IN = 256, OUT = D3;
    constexpr int RS = IN + 4;          // 260: LDS.128 phase-conflict-free
    __shared__ float W_s[32 * RS];      // 33.3 KB
    __shared__ float h_s[16 * RS];      // 16.6 KB

    const int tx = threadIdx.x;         // 0..31 -> output
    const int ty = threadIdx.y;         // 0..7  -> batch pair
    const int tid = ty * 32 + tx;
    const int o0 = blockIdx.x * 32;
    const int b0 = blockIdx.y * 16;
    const int bl = ty * 2;

    // Stage W tile: 32 rows x 256 k (float4, gmem coalesced).
    for (int idx = tid; idx < 32 * (IN / 4); idx += 256) {
        int o = idx >> 6;
        int k4 = idx & 63;
        float4 v = *reinterpret_cast<const float4*>(&We[(o0 + o) * IN + k4 * 4]);
        *reinterpret_cast<float4*>(&W_s[o * RS + k4 * 4]) = v;
    }
    // Stage h tile: 16 rows x 256 k.
    for (int idx = tid; idx < 16 * (IN / 4); idx += 256) {
        int b = idx >> 6;
        int k4 = idx & 63;
        float4 v = *reinterpret_cast<const float4*>(&h_in[(b0 + b) * IN + k4 * 4]);
        *reinterpret_cast<float4*>(&h_s[b * RS + k4 * 4]) = v;
    }
    __syncthreads();

    const float* wp  = &W_s[tx * RS];
    const float* hp0 = &h_s[bl * RS];
    const float* hp1 = &h_s[(bl + 1) * RS];

    float acc0 = 0.f, acc1 = 0.f, acc2 = 0.f, acc3 = 0.f;

    // Software pipeline: cur regs / nxt regs.
    float4 wc  = *reinterpret_cast<const float4*>(wp);
    float4 h0c = *reinterpret_cast<const float4*>(hp0);
    float4 h1c = *reinterpret_cast<const float4*>(hp1);

#pragma unroll
    for (int k = 0; k < IN - 4; k += 4) {
        // Prefetch next iteration (independent of the FMAs below).
        float4 wn  = *reinterpret_cast<const float4*>(wp  + k + 4);
        float4 h0n = *reinterpret_cast<const float4*>(hp0 + k + 4);
        float4 h1n = *reinterpret_cast<const float4*>(hp1 + k + 4);
        // Compute on current.
        acc0 += wc.x * h0c.x + wc.y * h0c.y;
        acc1 += wc.z * h0c.z + wc.w * h0c.w;
        acc2 += wc.x * h1c.x + wc.y * h1c.y;
        acc3 += wc.z * h1c.z + wc.w * h1c.w;
        wc = wn; h0c = h0n; h1c = h1n;
    }
    // Epilogue iteration.
    acc0 += wc.x * h0c.x + wc.y * h0c.y;
    acc1 += wc.z * h0c.z + wc.w * h0c.w;
    acc2 += wc.x * h1c.x + wc.y * h1c.y;
    acc3 += wc.z * h1c.z + wc.w * h1c.w;

    float bb = bias[o0 + tx];
    out[(b0 + bl)     * OUT + o0 + tx] = acc0 + acc1 + bb;
    out[(b0 + bl + 1) * OUT + o0 + tx] = acc2 + acc3 + bb;
}

extern "C" void kernel_launch(void* const* d_in, const int* in_sizes, int n_in,
                              void* d_out, int out_size) {
    // Resolve input ordering at runtime (dict vs signature order).
    const float *x, *W0, *b0, *W1, *b1, *W2, *b2;
    const int *f0, *f1, *f2;
    x = (const float*)d_in[0];
    if (in_sizes[4] == 256) {
        // signature order: x, W0,b0, W1,b1, W2,b2, f0,f1,f2
        W0 = (const float*)d_in[1]; b0 = (const float*)d_in[2];
        W1 = (const float*)d_in[3]; b1 = (const float*)d_in[4];
        W2 = (const float*)d_in[5]; b2 = (const float*)d_in[6];
        f0 = (const int*)d_in[7];  f1 = (const int*)d_in[8];  f2 = (const int*)d_in[9];
    } else {
        // dict order: x, W0,b0,f0, W1,b1,f1, W2,b2,f2
        W0 = (const float*)d_in[1]; b0 = (const float*)d_in[2]; f0 = (const int*)d_in[3];
        W1 = (const float*)d_in[4]; b1 = (const float*)d_in[5]; f1 = (const int*)d_in[6];
        W2 = (const float*)d_in[7]; b2 = (const float*)d_in[8]; f2 = (const int*)d_in[9];
    }

    float *dWe0, *dWe1, *dWe2, *dh1, *dh2;
    cudaGetSymbolAddress((void**)&dWe0, g_We0);
    cudaGetSymbolAddress((void**)&dWe1, g_We1);
    cudaGetSymbolAddress((void**)&dWe2, g_We2);
    cudaGetSymbolAddress((void**)&dh1, g_h1);
    cudaGetSymbolAddress((void**)&dh2, g_h2);

    float* out = (float*)d_out;

    prep_we_kernel<<<256, 256>>>(W0, f0, W1, f1, W2, f2);

    dim3 blk(32, 8);
    // Layer 0: x -> h1 (MUFU tanh, at floor)
    layer_tanh_kernel<D0><<<dim3(D1 / 32, BATCH / 8), blk>>>(x, dWe0, b0, dh1, D1);
    // Layer 1: h1 -> h2 (MUFU tanh, at floor)
    layer_tanh_kernel<D1><<<dim3(D2 / 32, BATCH / 8), blk>>>(dh1, dWe1, b1, dh2, D2);
    // Layer 2: h2 -> out, identity GEMM (pipelined, 32o x 16b, grid 512)
    layer_lin_kernel<<<dim3(D3 / 32, BATCH / 16), blk>>>(dh2, dWe2, b2, out);
}